// round 15
// baseline (speedup 1.0000x reference)
#include <cuda_runtime.h>
#include <cuda_bf16.h>
#include <math.h>
#include <stdint.h>

#define N_PTS   16384
#define N_CODE  8192
#define E_DIM   256
#define Z_ELEMS 4194304            // 16*256*32*32
#define ONE_HOT_ELEMS 134217728LL  // 16384*8192

#define WINDOW  2.5e-4f            // >= 2*delta_max of bf16-approx error, with margin
#define NSLOT   32                 // 8 holder groups/row * top-4

// smem layout (bytes): sA [128][264] bf16, sB x2 [128][264] bf16 (full tile, dbl-buffered)
#define SA_STRIDE 264
#define SB_STRIDE 264
#define SA_BYTES  (128 * SA_STRIDE * 2)          // 67584
#define SB_BYTES  (128 * SB_STRIDE * 2)          // 67584
#define DSMEM_BYTES (SA_BYTES + 2 * SB_BYTES)    // 202752

// ---------------- device scratch ----------------
__device__ int   g_counts[N_CODE];
__device__ float g_zsq[N_PTS];
__device__ float g_loss_part[N_PTS];
__device__ __nv_bfloat16 g_ebf[N_CODE * E_DIM];
__device__ float g_cand_v[N_PTS * NSLOT];
__device__ int   g_cand_j[N_PTS * NSLOT];
__device__ unsigned long long g_best_key[N_PTS];   // (monotone(s) << 32) | j
__device__ int   g_nflag;
__device__ int   g_flaglist[N_PTS * 8];            // entry = n*8 + group

__device__ __forceinline__ uint32_t fmono(float f) {
    uint32_t b = __float_as_uint(f);
    return b ^ ((b & 0x80000000u) ? 0xFFFFFFFFu : 0x80000000u);
}

// ---------------- zero scratch ----------------
__global__ void vq_zero_kernel() {
    int i = blockIdx.x * blockDim.x + threadIdx.x;
    if (i < N_CODE) g_counts[i] = 0;
    if (i == 0) g_nflag = 0;
}

// ---------------- e_w -> bf16 ----------------
__global__ void vq_ebf_kernel(const float* __restrict__ e_w) {
    int i = blockIdx.x * blockDim.x + threadIdx.x;
    if (i < N_CODE * E_DIM) g_ebf[i] = __float2bfloat16_rn(e_w[i]);
}

// ---------------- z_sq: bit-exact XLA row reduction (proven R5) ----------------
__global__ void vq_zsq_kernel(const float* __restrict__ z) {
    __shared__ float wsum[4];
    const int n = blockIdx.x;
    const int t = threadIdx.x;
    const int b = n >> 10, nlow = n & 1023;
    const float* base = z + (size_t)b * 262144 + nlow;
    const float x0 = base[(size_t)(2 * t)     * 1024];
    const float x1 = base[(size_t)(2 * t + 1) * 1024];
    float v = __fadd_rn(__fmul_rn(x0, x0), __fmul_rn(x1, x1));
    #pragma unroll
    for (int off = 16; off > 0; off >>= 1)
        v = __fadd_rn(v, __shfl_down_sync(0xffffffffu, v, off));
    if ((t & 31) == 0) wsum[t >> 5] = v;
    __syncthreads();
    if (t == 0)
        g_zsq[n] = __fadd_rn(__fadd_rn(wsum[0], wsum[2]),
                             __fadd_rn(wsum[1], wsum[3]));
}

// ---------------- bf16 mma.sync approx GEMM + per-row top-4 candidates ----------------
__device__ __forceinline__ void mma_bf16(float* c, const uint32_t* a,
                                         uint32_t b0, uint32_t b1) {
    asm volatile(
        "mma.sync.aligned.m16n8k16.row.col.f32.bf16.bf16.f32 "
        "{%0,%1,%2,%3}, {%4,%5,%6,%7}, {%8,%9}, {%0,%1,%2,%3};"
        : "+f"(c[0]), "+f"(c[1]), "+f"(c[2]), "+f"(c[3])
        : "r"(a[0]), "r"(a[1]), "r"(a[2]), "r"(a[3]), "r"(b0), "r"(b1));
}
__device__ __forceinline__ void ldmatrix_x4(uint32_t* r, uint32_t saddr) {
    asm volatile("ldmatrix.sync.aligned.m8n8.x4.shared.b16 {%0,%1,%2,%3}, [%4];"
                 : "=r"(r[0]), "=r"(r[1]), "=r"(r[2]), "=r"(r[3]) : "r"(saddr));
}

// 512 threads / 16 warps: warp w covers rows [wm*16, wm*16+16) (wm=w&7),
// cols [wn*64, wn*64+64) (wn=w>>3). Per-thread candidate-group structure
// (j = jt*128 + wn*64 + nf*8 + 2t + (e&1); 8 groups/row, top-4) is IDENTICAL
// to the proven R13/R14 layout -> resolve/fixup unchanged.
__global__ __launch_bounds__(512, 1)
void vq_mma_kernel(const float* __restrict__ z, float2* __restrict__ one_hot_zero) {
    extern __shared__ char sm[];
    __nv_bfloat16* sA  = (__nv_bfloat16*)sm;                       // [128][264]
    __nv_bfloat16* sB0 = (__nv_bfloat16*)(sm + SA_BYTES);          // [128][264]
    __nv_bfloat16* sB1 = (__nv_bfloat16*)(sm + SA_BYTES + SB_BYTES);
    const uint32_t sA_u  = (uint32_t)__cvta_generic_to_shared(sA);
    const uint32_t sB0_u = (uint32_t)__cvta_generic_to_shared(sB0);
    const uint32_t sB1_u = (uint32_t)__cvta_generic_to_shared(sB1);

    const int tid  = threadIdx.x;
    const int lane = tid & 31;
    const int w    = tid >> 5;
    const int g    = lane >> 2;
    const int t    = lane & 3;
    const int wm   = w & 7;          // row tile: 16 rows
    const int wn   = w >> 3;         // col tile: 64 cols (0..1)
    const int r0   = blockIdx.x * 128;
    const float* zbase = z + (size_t)(r0 >> 10) * 262144 + (r0 & 1023);

    const int sel   = lane >> 3;
    const int row8  = lane & 7;
    const int selm8 = (sel & 1) * 8;
    const int selk8 = (sel >> 1) * 8;

    {   // A phase: z rows -> bf16 resident smem [m][k] (512 threads)
        const int n = tid & 127;
        const int kpar = tid >> 7;       // 0..3
        #pragma unroll 8
        for (int i = 0; i < 64; i++) {
            const int k = 4 * i + kpar;
            sA[n * SA_STRIDE + k] = __float2bfloat16_rn(zbase[(size_t)k * 1024 + n]);
        }
    }

    float myZsq[2];
    #pragma unroll
    for (int r = 0; r < 2; r++)
        myZsq[r] = g_zsq[r0 + wm * 16 + g + r * 8];

    const float INF = __int_as_float(0x7f800000);
    float cv[2][4]; int cj[2][4];
    #pragma unroll
    for (int r = 0; r < 2; r++)
        #pragma unroll
        for (int i = 0; i < 4; i++) { cv[r][i] = INF; cj[r][i] = 0x7fffffff; }

    // B tile loader: part q = k-range [q*64, q*64+64) for all 128 rows.
    // 512 threads: row bn = tid>>2, quarter bq = tid&3 (16 bf16 = 2 uint4)
    const int bn = tid >> 2;
    const int bq = tid & 3;
    uint4 pf[2];
    auto ldpart = [&](int jt, int q) {
        const __nv_bfloat16* src = g_ebf
            + (size_t)(jt * 128 + bn) * E_DIM + q * 64 + bq * 16;
        pf[0] = ((const uint4*)src)[0];
        pf[1] = ((const uint4*)src)[1];
    };
    auto stpart = [&](__nv_bfloat16* buf, int q) {
        uint4* d = (uint4*)((char*)buf + bn * (SB_STRIDE * 2) + q * 128 + bq * 32);
        d[0] = pf[0]; d[1] = pf[1];
    };

    float acc[8][4];

    // prologue: tile 0 into sB0
    #pragma unroll
    for (int q = 0; q < 4; q++) { ldpart(0, q); stpart(sB0, q); }
    __syncthreads();

    const uint32_t aRow = (uint32_t)((wm * 16 + selm8 + row8) * SA_STRIDE) * 2u;
    uint32_t bRow[4];
    #pragma unroll
    for (int nfp = 0; nfp < 4; nfp++)
        bRow[nfp] = (uint32_t)((wn * 64 + nfp * 16 + selk8 + row8) * SB_STRIDE) * 2u;
    const uint32_t bKoff = (uint32_t)selm8 * 2u;
    const uint32_t aKoff = (uint32_t)selk8 * 2u;

    const float2 zero2 = make_float2(0.f, 0.f);

    #pragma unroll 1
    for (int jt = 0; jt < 64; jt++) {
        const int cur = jt & 1;
        const uint32_t B_u = cur ? sB1_u : sB0_u;
        __nv_bfloat16* Balt = cur ? sB0 : sB1;

        #pragma unroll
        for (int nf = 0; nf < 8; nf++)
            #pragma unroll
            for (int e = 0; e < 4; e++) acc[nf][e] = 0.f;

        #pragma unroll 1
        for (int q = 0; q < 4; q++) {
            if (jt + 1 < 64) ldpart(jt + 1, q);     // prefetch next tile's part q

            #pragma unroll
            for (int k16 = 0; k16 < 4; k16++) {
                const uint32_t kk = (uint32_t)(q * 64 + k16 * 16) * 2u;
                uint32_t aF[4];
                ldmatrix_x4(aF, sA_u + aRow + kk + aKoff);
                const uint32_t kgB = kk + bKoff;
                #pragma unroll
                for (int nfp = 0; nfp < 4; nfp++) {
                    uint32_t bF[4];
                    ldmatrix_x4(bF, B_u + bRow[nfp] + kgB);
                    mma_bf16(acc[nfp * 2],     aF, bF[0], bF[1]);
                    mma_bf16(acc[nfp * 2 + 1], aF, bF[2], bF[3]);
                }
            }
            if (jt + 1 < 64) stpart(Balt, q);       // store into idle buffer
        }

        // epilogue: s = fl(zsq - 2m), insert into per-row sorted top-4
        #pragma unroll
        for (int nf = 0; nf < 8; nf++)
            #pragma unroll
            for (int e = 0; e < 4; e++) {
                const int r = e >> 1;
                const int j = jt * 128 + wn * 64 + nf * 8 + 2 * t + (e & 1);
                const float s = __fsub_rn(myZsq[r], __fmul_rn(2.0f, acc[nf][e]));
                if (s < cv[r][3]) {
                    cv[r][3] = s; cj[r][3] = j;
                    if (s < cv[r][2]) {
                        cv[r][3] = cv[r][2]; cj[r][3] = cj[r][2]; cv[r][2] = s; cj[r][2] = j;
                        if (s < cv[r][1]) {
                            cv[r][2] = cv[r][1]; cj[r][2] = cj[r][1]; cv[r][1] = s; cj[r][1] = j;
                            if (s < cv[r][0]) {
                                cv[r][1] = cv[r][0]; cj[r][1] = cj[r][0]; cv[r][0] = s; cj[r][0] = j;
                            }
                        }
                    }
                }
            }

        // stream zeros into one_hot: 128 blocks x 64 jt x 64KB == 512MB exactly
        if (one_hot_zero) {
            float2* dst = one_hot_zero + ((size_t)blockIdx.x * 64 + jt) * 8192;
            #pragma unroll
            for (int u = 0; u < 16; u++)
                __stcs(dst + u * 512 + tid, zero2);
        }

        __syncthreads();   // single barrier per jt
    }

    // write candidates: row n, slot group (wn*4 + t)*4 + i  (same layout as R13)
    #pragma unroll
    for (int r = 0; r < 2; r++) {
        const int n = r0 + wm * 16 + g + r * 8;
        const int sbase = (wn * 4 + t) * 4;
        #pragma unroll
        for (int i = 0; i < 4; i++) {
            g_cand_v[(size_t)n * NSLOT + sbase + i] = cv[r][i];
            g_cand_j[(size_t)n * NSLOT + sbase + i] = cj[r][i];
        }
    }
}

// ---------------- resolve: exact best over in-window candidates -> key;
//                  overflowed groups -> worklist (group-restricted fixup) ----------------
__global__ void vq_resolve_kernel(const float* __restrict__ z, const float* __restrict__ e_w) {
    const int gw   = (blockIdx.x * blockDim.x + threadIdx.x) >> 5;
    const int lane = threadIdx.x & 31;
    if (gw >= N_PTS) return;
    const int n = gw;
    const float zsq = g_zsq[n];

    const float v = g_cand_v[(size_t)n * NSLOT + lane];
    const int  jc = g_cand_j[(size_t)n * NSLOT + lane];
    float vmin = v;
    #pragma unroll
    for (int o = 16; o > 0; o >>= 1) vmin = fminf(vmin, __shfl_xor_sync(0xffffffffu, vmin, o));
    const float thresh = vmin + WINDOW;

    if (((lane & 3) == 3) && (v <= thresh)) {
        const int slot = atomicAdd(&g_nflag, 1);
        g_flaglist[slot] = n * 8 + (lane >> 2);
    }

    unsigned long long key = 0xFFFFFFFFFFFFFFFFull;
    if (v <= thresh) {
        float m = 0.f;
        const float* zrow = z + (size_t)(n >> 10) * 262144 + (n & 1023);
        const float* er = e_w + (size_t)jc * E_DIM;
        #pragma unroll 8
        for (int k = 0; k < E_DIM; k++)
            m = fmaf(__ldg(zrow + (size_t)k * 1024), __ldg(er + k), m);
        const float s = __fsub_rn(zsq, __fmul_rn(2.0f, m));
        key = ((unsigned long long)fmono(s) << 32) | (unsigned)jc;
    }
    #pragma unroll
    for (int o = 16; o > 0; o >>= 1) {
        const unsigned long long ok = __shfl_down_sync(0xffffffffu, key, o);
        if (ok < key) key = ok;
    }
    if (lane == 0) g_best_key[n] = key;
}

// ---------------- fixup: block per (point, overflowed-group): exact scan of 1024 j ----------------
__global__ __launch_bounds__(256)
void vq_fixup_kernel(const float* __restrict__ z, const float* __restrict__ e_w) {
    __shared__ unsigned long long sK[256];
    const int tid = threadIdx.x;
    const int nflag = g_nflag;

    for (int it = blockIdx.x; it < nflag; it += gridDim.x) {
        const int entry = g_flaglist[it];
        const int n  = entry >> 3;
        const int gg = entry & 7;
        const int wn = gg >> 2;
        const int t2 = gg & 3;
        const float zsq = g_zsq[n];
        const float* zrow = z + (size_t)(n >> 10) * 262144 + (n & 1023);

        unsigned long long key = 0xFFFFFFFFFFFFFFFFull;
        #pragma unroll
        for (int i = 0; i < 4; i++) {
            const int c = tid * 4 + i;
            const int jt = c >> 4;
            const int nf = (c >> 1) & 7;
            const int b  = c & 1;
            const int j  = jt * 128 + wn * 64 + nf * 8 + 2 * t2 + b;
            float m = 0.f;
            const float* er = e_w + (size_t)j * E_DIM;
            #pragma unroll 8
            for (int k = 0; k < E_DIM; k++)
                m = fmaf(__ldg(zrow + (size_t)k * 1024), __ldg(er + k), m);
            const float s = __fsub_rn(zsq, __fmul_rn(2.0f, m));
            const unsigned long long kk =
                ((unsigned long long)fmono(s) << 32) | (unsigned)j;
            if (kk < key) key = kk;
        }
        sK[tid] = key;
        __syncthreads();
        for (int o = 128; o > 0; o >>= 1) {
            if (tid < o && sK[tid + o] < sK[tid]) sK[tid] = sK[tid + o];
            __syncthreads();
        }
        if (tid == 0) atomicMin(&g_best_key[n], sK[0]);
        __syncthreads();
    }
}

// ---------------- scatter: one_hot ones, indices-as-float, histogram ----------------
__global__ void vq_scatter_kernel(float* __restrict__ one_hot,
                                  float* __restrict__ out_idx,
                                  int write_onehot, int write_idx) {
    const int n = blockIdx.x * blockDim.x + threadIdx.x;
    if (n >= N_PTS) return;
    const int idx = (int)(g_best_key[n] & 0xFFFFFFFFull);
    atomicAdd(&g_counts[idx], 1);
    if (write_onehot) one_hot[(size_t)n * N_CODE + idx] = 1.0f;
    if (write_idx)    out_idx[n] = (float)idx;
}

// ---------------- z_q_st + per-block loss partials ----------------
__global__ void vq_zq_kernel(const float* __restrict__ z,
                             const float* __restrict__ e_w,
                             float* __restrict__ out_zq, int write_zq) {
    __shared__ float sred[8];
    const int e = blockIdx.x * blockDim.x + threadIdx.x;
    const int b    = e >> 18;
    const int rem  = e & 262143;
    const int c    = rem >> 10;
    const int nlow = rem & 1023;
    const int n    = (b << 10) + nlow;
    const float zv = z[e];
    const int idx  = (int)(g_best_key[n] & 0xFFFFFFFFull);
    const float q  = e_w[(size_t)idx * E_DIM + c];
    const float d  = __fsub_rn(q, zv);
    if (write_zq) out_zq[e] = __fadd_rn(zv, d);
    float s = __fmul_rn(d, d);
    #pragma unroll
    for (int o = 16; o > 0; o >>= 1) s += __shfl_down_sync(0xffffffffu, s, o);
    const int lane = threadIdx.x & 31, wid = threadIdx.x >> 5;
    if (lane == 0) sred[wid] = s;
    __syncthreads();
    if (wid == 0) {
        float v = (lane < 8) ? sred[lane] : 0.f;
        #pragma unroll
        for (int o = 4; o > 0; o >>= 1) v += __shfl_down_sync(0xffffffffu, v, o);
        if (lane == 0) g_loss_part[blockIdx.x] = v;
    }
}

// ---------------- finalize: loss + perplexity ----------------
__global__ void vq_finalize_kernel(float* __restrict__ out,
                                   long long loss_off, long long ppl_off,
                                   int write_loss, int write_ppl) {
    __shared__ float sh[256];
    const int tid = threadIdx.x;
    float ls = 0.f;
    for (int i = tid; i < N_PTS; i += 256) ls += g_loss_part[i];
    sh[tid] = ls;
    __syncthreads();
    for (int o = 128; o > 0; o >>= 1) { if (tid < o) sh[tid] += sh[tid + o]; __syncthreads(); }
    const float loss_sum = sh[0];
    __syncthreads();
    float ps = 0.f;
    for (int j = tid; j < N_CODE; j += 256) {
        const float p = (float)g_counts[j] * (1.0f / (float)N_PTS);
        ps += p * logf(p + 1e-10f);
    }
    sh[tid] = ps;
    __syncthreads();
    for (int o = 128; o > 0; o >>= 1) { if (tid < o) sh[tid] += sh[tid + o]; __syncthreads(); }
    if (tid == 0) {
        if (write_loss) out[loss_off] = loss_sum * (1.25f / (float)Z_ELEMS);
        if (write_ppl)  out[ppl_off]  = expf(-sh[0]);
    }
}

// ---------------- launch ----------------
extern "C" void kernel_launch(void* const* d_in, const int* in_sizes, int n_in,
                              void* d_out, int out_size) {
    const float* z   = (const float*)d_in[0];
    const float* e_w = (const float*)d_in[1];
    float* out = (float*)d_out;

    const long long sizes[5] = {1, Z_ELEMS, 1, ONE_HOT_ELEMS, N_PTS};
    long long off[5];
    int present[5];
    long long cum = 0;
    for (int i = 0; i < 5; i++) {
        off[i] = cum;
        present[i] = (cum + sizes[i] <= (long long)out_size) ? 1 : 0;
        if (present[i]) cum += sizes[i];
    }

    cudaFuncSetAttribute(vq_mma_kernel,
                         cudaFuncAttributeMaxDynamicSharedMemorySize, DSMEM_BYTES);

    vq_zero_kernel<<<(N_CODE + 255) / 256, 256>>>();
    vq_ebf_kernel<<<(N_CODE * E_DIM) / 256, 256>>>(e_w);
    vq_zsq_kernel<<<N_PTS, 128>>>(z);
    vq_mma_kernel<<<N_PTS / 128, 512, DSMEM_BYTES>>>(z,
        present[3] ? (float2*)(out + off[3]) : (float2*)nullptr);
    vq_resolve_kernel<<<(N_PTS * 32) / 128, 128>>>(z, e_w);
    vq_fixup_kernel<<<592, 256>>>(z, e_w);
    vq_scatter_kernel<<<(N_PTS + 255) / 256, 256>>>(
        present[3] ? out + off[3] : out,
        present[4] ? out + off[4] : out,
        present[3], present[4]);
    vq_zq_kernel<<<Z_ELEMS / 256, 256>>>(z, e_w,
        present[1] ? out + off[1] : out, present[1]);
    vq_finalize_kernel<<<1, 256>>>(out, off[0], off[2], present[0], present[2]);
}

// round 17
// speedup vs baseline: 1.4068x; 1.4068x over previous
#include <cuda_runtime.h>
#include <cuda_bf16.h>
#include <math.h>
#include <stdint.h>

#define N_PTS   16384
#define N_CODE  8192
#define E_DIM   256
#define Z_ELEMS 4194304            // 16*256*32*32
#define ONE_HOT_ELEMS 134217728LL  // 16384*8192

#define WINDOW  2.5e-4f            // >= 2*delta_max of bf16-approx error, with margin
#define NSLOT   32                 // 8 holder groups/row * top-4

// smem layout (bytes): sA [128][264] bf16, sB x2 [128][264] bf16 (full tile, dbl-buffered)
#define SA_STRIDE 264
#define SB_STRIDE 264
#define SA_BYTES  (128 * SA_STRIDE * 2)          // 67584
#define SB_BYTES  (128 * SB_STRIDE * 2)          // 67584
#define DSMEM_BYTES (SA_BYTES + 2 * SB_BYTES)    // 202752

// ---------------- device scratch ----------------
__device__ int   g_counts[N_CODE];
__device__ float g_zsq[N_PTS];
__device__ float g_loss_part[4096];
__device__ __align__(16) __nv_bfloat16 g_ebf[N_CODE * E_DIM];
__device__ float g_cand_v[N_PTS * NSLOT];
__device__ int   g_cand_j[N_PTS * NSLOT];
__device__ unsigned long long g_best_key[N_PTS];   // (monotone(s) << 32) | j
__device__ int   g_nflag;
__device__ int   g_flaglist[N_PTS * 8];            // entry = n*8 + group

__device__ __forceinline__ uint32_t fmono(float f) {
    uint32_t b = __float_as_uint(f);
    return b ^ ((b & 0x80000000u) ? 0xFFFFFFFFu : 0x80000000u);
}

// ---------------- e_w -> bf16 (+ zero scratch, fused) ----------------
__global__ void vq_ebf_kernel(const float* __restrict__ e_w) {
    int i = blockIdx.x * blockDim.x + threadIdx.x;
    if (i < N_CODE) g_counts[i] = 0;
    if (i == 0) g_nflag = 0;
    if (i < N_CODE * E_DIM) g_ebf[i] = __float2bfloat16_rn(e_w[i]);
}

// ---------------- z_sq: bit-exact XLA row reduction (proven R5) ----------------
__global__ void vq_zsq_kernel(const float* __restrict__ z) {
    __shared__ float wsum[4];
    const int n = blockIdx.x;
    const int t = threadIdx.x;
    const int b = n >> 10, nlow = n & 1023;
    const float* base = z + (size_t)b * 262144 + nlow;
    const float x0 = base[(size_t)(2 * t)     * 1024];
    const float x1 = base[(size_t)(2 * t + 1) * 1024];
    float v = __fadd_rn(__fmul_rn(x0, x0), __fmul_rn(x1, x1));
    #pragma unroll
    for (int off = 16; off > 0; off >>= 1)
        v = __fadd_rn(v, __shfl_down_sync(0xffffffffu, v, off));
    if ((t & 31) == 0) wsum[t >> 5] = v;
    __syncthreads();
    if (t == 0)
        g_zsq[n] = __fadd_rn(__fadd_rn(wsum[0], wsum[2]),
                             __fadd_rn(wsum[1], wsum[3]));
}

// ---------------- bf16 mma.sync approx GEMM + per-row top-4 candidates ----------------
__device__ __forceinline__ void mma_bf16(float* c, const uint32_t* a,
                                         uint32_t b0, uint32_t b1) {
    asm volatile(
        "mma.sync.aligned.m16n8k16.row.col.f32.bf16.bf16.f32 "
        "{%0,%1,%2,%3}, {%4,%5,%6,%7}, {%8,%9}, {%0,%1,%2,%3};"
        : "+f"(c[0]), "+f"(c[1]), "+f"(c[2]), "+f"(c[3])
        : "r"(a[0]), "r"(a[1]), "r"(a[2]), "r"(a[3]), "r"(b0), "r"(b1));
}
__device__ __forceinline__ void ldmatrix_x4(uint32_t* r, uint32_t saddr) {
    asm volatile("ldmatrix.sync.aligned.m8n8.x4.shared.b16 {%0,%1,%2,%3}, [%4];"
                 : "=r"(r[0]), "=r"(r[1]), "=r"(r[2]), "=r"(r[3]) : "r"(saddr));
}
#define CP_COMMIT() asm volatile("cp.async.commit_group;" ::: "memory")
#define CP_WAIT0()  asm volatile("cp.async.wait_group 0;" ::: "memory")

// 256 threads / 8 warps (R14 proven shape): warp w: rows [wm*32,+32) (wm=w&3),
// cols [wn*64,+64) (wn=w>>2). Candidate layout identical to R13/R14.
__global__ __launch_bounds__(256, 1)
void vq_mma_kernel(const float* __restrict__ z, float2* __restrict__ one_hot_zero) {
    extern __shared__ char sm[];
    __nv_bfloat16* sA  = (__nv_bfloat16*)sm;                       // [128][264]
    const uint32_t sA_u  = (uint32_t)__cvta_generic_to_shared(sA);
    const uint32_t sB0_u = sA_u + SA_BYTES;
    const uint32_t sB1_u = sA_u + SA_BYTES + SB_BYTES;

    const int tid  = threadIdx.x;
    const int lane = tid & 31;
    const int w    = tid >> 5;
    const int g    = lane >> 2;
    const int t    = lane & 3;
    const int wm   = w & 3;
    const int wn   = w >> 2;
    const int r0   = blockIdx.x * 128;
    const float* zbase = z + (size_t)(r0 >> 10) * 262144 + (r0 & 1023);

    const int sel   = lane >> 3;
    const int row8  = lane & 7;
    const int selm8 = (sel & 1) * 8;
    const int selk8 = (sel >> 1) * 8;

    {   // A phase: z rows -> bf16 resident smem [m][k]
        const int n = tid & 127;
        const int kpar = tid >> 7;
        #pragma unroll 8
        for (int i = 0; i < 128; i++) {
            const int k = 2 * i + kpar;
            sA[n * SA_STRIDE + k] = __float2bfloat16_rn(zbase[(size_t)k * 1024 + n]);
        }
    }

    float myZsq[4];
    #pragma unroll
    for (int r = 0; r < 4; r++)
        myZsq[r] = g_zsq[r0 + wm * 32 + (r >> 1) * 16 + g + (r & 1) * 8];

    const float INF = __int_as_float(0x7f800000);
    float cv[4][4]; int cj[4][4];
    #pragma unroll
    for (int r = 0; r < 4; r++)
        #pragma unroll
        for (int i = 0; i < 4; i++) { cv[r][i] = INF; cj[r][i] = 0x7fffffff; }

    // B tile loader via cp.async: part q of tile jt = k-range [q*64,+64), 128 rows.
    // thread: row bn = tid>>1, half bh = tid&1 (32 bf16 = 4 x 16B)
    const int bn = tid >> 1;
    const int bh = tid & 1;
    auto cp_part = [&](int jt, int q, uint32_t dstbuf) {
        const __nv_bfloat16* src = g_ebf
            + (size_t)(jt * 128 + bn) * E_DIM + q * 64 + bh * 32;
        const uint32_t dst = dstbuf + (uint32_t)(bn * (SB_STRIDE * 2) + q * 128 + bh * 64);
        #pragma unroll
        for (int i = 0; i < 4; i++)
            asm volatile("cp.async.cg.shared.global [%0], [%1], 16;"
                         :: "r"(dst + 16 * i), "l"(src + 8 * i) : "memory");
    };

    float acc[2][8][4];

    // prologue: tile 0 into sB0
    #pragma unroll
    for (int q = 0; q < 4; q++) cp_part(0, q, sB0_u);
    CP_COMMIT(); CP_WAIT0();
    __syncthreads();

    const uint32_t aRow0 = (uint32_t)((wm * 32 + selm8 + row8) * SA_STRIDE) * 2u;
    const uint32_t aRow1 = aRow0 + (uint32_t)(16 * SA_STRIDE) * 2u;
    uint32_t bRow[4];
    #pragma unroll
    for (int nfp = 0; nfp < 4; nfp++)
        bRow[nfp] = (uint32_t)((wn * 64 + nfp * 16 + selk8 + row8) * SB_STRIDE) * 2u;
    const uint32_t bKoff = (uint32_t)selm8 * 2u;
    const uint32_t aKoff = (uint32_t)selk8 * 2u;

    const float2 zero2 = make_float2(0.f, 0.f);

    #pragma unroll 1
    for (int jt = 0; jt < 64; jt++) {
        const int cur = jt & 1;
        const uint32_t B_u   = cur ? sB1_u : sB0_u;
        const uint32_t Balt_u = cur ? sB0_u : sB1_u;

        #pragma unroll
        for (int mf = 0; mf < 2; mf++)
            #pragma unroll
            for (int nf = 0; nf < 8; nf++)
                #pragma unroll
                for (int e = 0; e < 4; e++) acc[mf][nf][e] = 0.f;

        #pragma unroll 1
        for (int q = 0; q < 4; q++) {
            if (jt + 1 < 64) cp_part(jt + 1, q, Balt_u);   // async prefetch

            #pragma unroll
            for (int k16 = 0; k16 < 4; k16++) {
                const uint32_t kk = (uint32_t)(q * 64 + k16 * 16) * 2u;
                uint32_t aF[2][4];
                ldmatrix_x4(aF[0], sA_u + aRow0 + kk + aKoff);
                ldmatrix_x4(aF[1], sA_u + aRow1 + kk + aKoff);
                const uint32_t kgB = kk + bKoff;
                #pragma unroll
                for (int nfp = 0; nfp < 4; nfp++) {
                    uint32_t bF[4];
                    ldmatrix_x4(bF, B_u + bRow[nfp] + kgB);
                    mma_bf16(acc[0][nfp * 2],     aF[0], bF[0], bF[1]);
                    mma_bf16(acc[1][nfp * 2],     aF[1], bF[0], bF[1]);
                    mma_bf16(acc[0][nfp * 2 + 1], aF[0], bF[2], bF[3]);
                    mma_bf16(acc[1][nfp * 2 + 1], aF[1], bF[2], bF[3]);
                }
            }
        }
        CP_COMMIT();

        // epilogue: s = fl(zsq - 2m), insert into per-row sorted top-4
        #pragma unroll
        for (int mf = 0; mf < 2; mf++)
            #pragma unroll
            for (int nf = 0; nf < 8; nf++)
                #pragma unroll
                for (int e = 0; e < 4; e++) {
                    const int r = mf * 2 + (e >> 1);
                    const int j = jt * 128 + wn * 64 + nf * 8 + 2 * t + (e & 1);
                    const float s = __fsub_rn(myZsq[r], __fmul_rn(2.0f, acc[mf][nf][e]));
                    if (s < cv[r][3]) {
                        cv[r][3] = s; cj[r][3] = j;
                        if (s < cv[r][2]) {
                            cv[r][3] = cv[r][2]; cj[r][3] = cj[r][2]; cv[r][2] = s; cj[r][2] = j;
                            if (s < cv[r][1]) {
                                cv[r][2] = cv[r][1]; cj[r][2] = cj[r][1]; cv[r][1] = s; cj[r][1] = j;
                                if (s < cv[r][0]) {
                                    cv[r][1] = cv[r][0]; cj[r][1] = cj[r][0]; cv[r][0] = s; cj[r][0] = j;
                                }
                            }
                        }
                    }
                }

        // stream zeros into one_hot: 128 blocks x 64 jt x 64KB == 512MB exactly
        if (one_hot_zero) {
            float2* dst = one_hot_zero + ((size_t)blockIdx.x * 64 + jt) * 8192;
            #pragma unroll
            for (int u = 0; u < 32; u++)
                __stcs(dst + u * 256 + tid, zero2);
        }

        CP_WAIT0();
        __syncthreads();   // single barrier per jt: alt buffer complete, cur buffer free
    }

    #pragma unroll
    for (int r = 0; r < 4; r++) {
        const int n = r0 + wm * 32 + (r >> 1) * 16 + g + (r & 1) * 8;
        const int sbase = (wn * 4 + t) * 4;
        #pragma unroll
        for (int i = 0; i < 4; i++) {
            g_cand_v[(size_t)n * NSLOT + sbase + i] = cv[r][i];
            g_cand_j[(size_t)n * NSLOT + sbase + i] = cj[r][i];
        }
    }
}

// ---------------- resolve: exact best over in-window candidates -> key;
//                  overflowed groups -> worklist (group-restricted fixup) ----------------
__global__ void vq_resolve_kernel(const float* __restrict__ z, const float* __restrict__ e_w) {
    const int gw   = (blockIdx.x * blockDim.x + threadIdx.x) >> 5;
    const int lane = threadIdx.x & 31;
    if (gw >= N_PTS) return;
    const int n = gw;
    const float zsq = g_zsq[n];

    const float v = g_cand_v[(size_t)n * NSLOT + lane];
    const int  jc = g_cand_j[(size_t)n * NSLOT + lane];
    float vmin = v;
    #pragma unroll
    for (int o = 16; o > 0; o >>= 1) vmin = fminf(vmin, __shfl_xor_sync(0xffffffffu, vmin, o));
    const float thresh = vmin + WINDOW;

    if (((lane & 3) == 3) && (v <= thresh)) {
        const int slot = atomicAdd(&g_nflag, 1);
        g_flaglist[slot] = n * 8 + (lane >> 2);
    }

    unsigned long long key = 0xFFFFFFFFFFFFFFFFull;
    if (v <= thresh) {
        float m = 0.f;
        const float* zrow = z + (size_t)(n >> 10) * 262144 + (n & 1023);
        const float* er = e_w + (size_t)jc * E_DIM;
        #pragma unroll 8
        for (int k = 0; k < E_DIM; k++)
            m = fmaf(__ldg(zrow + (size_t)k * 1024), __ldg(er + k), m);
        const float s = __fsub_rn(zsq, __fmul_rn(2.0f, m));
        key = ((unsigned long long)fmono(s) << 32) | (unsigned)jc;
    }
    #pragma unroll
    for (int o = 16; o > 0; o >>= 1) {
        const unsigned long long ok = __shfl_down_sync(0xffffffffu, key, o);
        if (ok < key) key = ok;
    }
    if (lane == 0) g_best_key[n] = key;
}

// ---------------- fixup: block per (point, overflowed-group): exact scan of 1024 j ----------------
__global__ __launch_bounds__(256)
void vq_fixup_kernel(const float* __restrict__ z, const float* __restrict__ e_w) {
    __shared__ unsigned long long sK[256];
    const int tid = threadIdx.x;
    const int nflag = g_nflag;

    for (int it = blockIdx.x; it < nflag; it += gridDim.x) {
        const int entry = g_flaglist[it];
        const int n  = entry >> 3;
        const int gg = entry & 7;
        const int wn = gg >> 2;
        const int t2 = gg & 3;
        const float zsq = g_zsq[n];
        const float* zrow = z + (size_t)(n >> 10) * 262144 + (n & 1023);

        unsigned long long key = 0xFFFFFFFFFFFFFFFFull;
        #pragma unroll
        for (int i = 0; i < 4; i++) {
            const int c = tid * 4 + i;
            const int jt = c >> 4;
            const int nf = (c >> 1) & 7;
            const int b  = c & 1;
            const int j  = jt * 128 + wn * 64 + nf * 8 + 2 * t2 + b;
            float m = 0.f;
            const float* er = e_w + (size_t)j * E_DIM;
            #pragma unroll 8
            for (int k = 0; k < E_DIM; k++)
                m = fmaf(__ldg(zrow + (size_t)k * 1024), __ldg(er + k), m);
            const float s = __fsub_rn(zsq, __fmul_rn(2.0f, m));
            const unsigned long long kk =
                ((unsigned long long)fmono(s) << 32) | (unsigned)j;
            if (kk < key) key = kk;
        }
        sK[tid] = key;
        __syncthreads();
        for (int o = 128; o > 0; o >>= 1) {
            if (tid < o && sK[tid + o] < sK[tid]) sK[tid] = sK[tid + o];
            __syncthreads();
        }
        if (tid == 0) atomicMin(&g_best_key[n], sK[0]);
        __syncthreads();
    }
}

// ---------------- scatter: one_hot ones, indices-as-float, histogram ----------------
__global__ void vq_scatter_kernel(float* __restrict__ one_hot,
                                  float* __restrict__ out_idx,
                                  int write_onehot, int write_idx) {
    const int n = blockIdx.x * blockDim.x + threadIdx.x;
    if (n >= N_PTS) return;
    const int idx = (int)(g_best_key[n] & 0xFFFFFFFFull);
    atomicAdd(&g_counts[idx], 1);
    if (write_onehot) one_hot[(size_t)n * N_CODE + idx] = 1.0f;
    if (write_idx)    out_idx[n] = (float)idx;
}

// ---------------- z_q_st + per-block loss partials (float4 z-loads, scalar stores:
//                  out+off[1] is only 4-byte aligned!) ----------------
__global__ void vq_zq_kernel(const float* __restrict__ z,
                             const float* __restrict__ e_w,
                             float* __restrict__ out_zq, int write_zq) {
    __shared__ float sred[8];
    const int e4 = (blockIdx.x * blockDim.x + threadIdx.x) * 4;   // 0..4194300, step 4
    const int b    = e4 >> 18;
    const int rem  = e4 & 262143;
    const int c    = rem >> 10;
    const int nlow = rem & 1023;                // multiple of 4, never crosses 1024
    const int n0   = (b << 10) + nlow;
    const float4 zv = *(const float4*)(z + e4);
    float dv[4];
    float ov[4];
    #pragma unroll
    for (int i = 0; i < 4; i++) {
        const int idx = (int)(g_best_key[n0 + i] & 0xFFFFFFFFull);
        const float q = e_w[(size_t)idx * E_DIM + c];
        const float zz = (i == 0) ? zv.x : (i == 1) ? zv.y : (i == 2) ? zv.z : zv.w;
        dv[i] = __fsub_rn(q, zz);
        ov[i] = __fadd_rn(zz, dv[i]);
    }
    if (write_zq) {
        #pragma unroll
        for (int i = 0; i < 4; i++) out_zq[e4 + i] = ov[i];   // scalar: 4B-aligned safe
    }
    float s = __fmul_rn(dv[0], dv[0]);
    #pragma unroll
    for (int i = 1; i < 4; i++) s = fmaf(dv[i], dv[i], s);
    #pragma unroll
    for (int o = 16; o > 0; o >>= 1) s += __shfl_down_sync(0xffffffffu, s, o);
    const int lane = threadIdx.x & 31, wid = threadIdx.x >> 5;
    if (lane == 0) sred[wid] = s;
    __syncthreads();
    if (wid == 0) {
        float v = (lane < 8) ? sred[lane] : 0.f;
        #pragma unroll
        for (int o = 4; o > 0; o >>= 1) v += __shfl_down_sync(0xffffffffu, v, o);
        if (lane == 0) g_loss_part[blockIdx.x] = v;
    }
}

// ---------------- finalize: loss + perplexity ----------------
__global__ void vq_finalize_kernel(float* __restrict__ out,
                                   long long loss_off, long long ppl_off,
                                   int write_loss, int write_ppl) {
    __shared__ float sh[256];
    const int tid = threadIdx.x;
    float ls = 0.f;
    for (int i = tid; i < 4096; i += 256) ls += g_loss_part[i];
    sh[tid] = ls;
    __syncthreads();
    for (int o = 128; o > 0; o >>= 1) { if (tid < o) sh[tid] += sh[tid + o]; __syncthreads(); }
    const float loss_sum = sh[0];
    __syncthreads();
    float ps = 0.f;
    for (int j = tid; j < N_CODE; j += 256) {
        const float p = (float)g_counts[j] * (1.0f / (float)N_PTS);
        ps += p * logf(p + 1e-10f);
    }
    sh[tid] = ps;
    __syncthreads();
    for (int o = 128; o > 0; o >>= 1) { if (tid < o) sh[tid] += sh[tid + o]; __syncthreads(); }
    if (tid == 0) {
        if (write_loss) out[loss_off] = loss_sum * (1.25f / (float)Z_ELEMS);
        if (write_ppl)  out[ppl_off]  = expf(-sh[0]);
    }
}

// ---------------- launch ----------------
extern "C" void kernel_launch(void* const* d_in, const int* in_sizes, int n_in,
                              void* d_out, int out_size) {
    const float* z   = (const float*)d_in[0];
    const float* e_w = (const float*)d_in[1];
    float* out = (float*)d_out;

    const long long sizes[5] = {1, Z_ELEMS, 1, ONE_HOT_ELEMS, N_PTS};
    long long off[5];
    int present[5];
    long long cum = 0;
    for (int i = 0; i < 5; i++) {
        off[i] = cum;
        present[i] = (cum + sizes[i] <= (long long)out_size) ? 1 : 0;
        if (present[i]) cum += sizes[i];
    }

    cudaFuncSetAttribute(vq_mma_kernel,
                         cudaFuncAttributeMaxDynamicSharedMemorySize, DSMEM_BYTES);

    vq_ebf_kernel<<<(N_CODE * E_DIM) / 256, 256>>>(e_w);
    vq_zsq_kernel<<<N_PTS, 128>>>(z);
    vq_mma_kernel<<<N_PTS / 128, 256, DSMEM_BYTES>>>(z,
        present[3] ? (float2*)(out + off[3]) : (float2*)nullptr);
    vq_resolve_kernel<<<(N_PTS * 32) / 128, 128>>>(z, e_w);
    vq_fixup_kernel<<<592, 256>>>(z, e_w);
    vq_scatter_kernel<<<(N_PTS + 255) / 256, 256>>>(
        present[3] ? out + off[3] : out,
        present[4] ? out + off[4] : out,
        present[3], present[4]);
    vq_zq_kernel<<<Z_ELEMS / 4 / 256, 256>>>(z, e_w,
        present[1] ? out + off[1] : out, present[1]);
    vq_finalize_kernel<<<1, 256>>>(out, off[0], off[2], present[0], present[2]);
}